// round 11
// baseline (speedup 1.0000x reference)
#include <cuda_runtime.h>
#include <cuda_bf16.h>
#include <math.h>
#include <stdint.h>

#define N_TOK 65536
#define DIM   256
#define KEMB  1024
#define MARGIN 0.004f

// ======================= helpers ===========================================
__device__ __forceinline__ uint32_t smem_to_u32(const void* p) {
    uint32_t a;
    asm("{ .reg .u64 t; cvta.to.shared.u64 t, %1; cvt.u32.u64 %0, t; }"
        : "=r"(a) : "l"(p));
    return a;
}
#define CP_ASYNC16(dst, src) \
    asm volatile("cp.async.cg.shared.global [%0], [%1], 16;" :: "r"(dst), "l"(src))
#define CP_COMMIT() asm volatile("cp.async.commit_group;" ::: "memory")
#define CP_WAIT(n)  asm volatile("cp.async.wait_group %0;" :: "n"(n) : "memory")

__device__ __forceinline__ void ldm_x4(uint32_t* r, uint32_t addr) {
    asm volatile("ldmatrix.sync.aligned.m8n8.x4.shared.b16 {%0,%1,%2,%3}, [%4];"
        : "=r"(r[0]), "=r"(r[1]), "=r"(r[2]), "=r"(r[3]) : "r"(addr));
}
__device__ __forceinline__ void mma_bf16(float* c, const uint32_t* a,
                                         uint32_t b0, uint32_t b1) {
    asm volatile(
        "mma.sync.aligned.m16n8k16.row.col.f32.bf16.bf16.f32 "
        "{%0,%1,%2,%3}, {%4,%5,%6,%7}, {%8,%9}, {%0,%1,%2,%3};"
        : "+f"(c[0]), "+f"(c[1]), "+f"(c[2]), "+f"(c[3])
        : "r"(a[0]), "r"(a[1]), "r"(a[2]), "r"(a[3]), "r"(b0), "r"(b1));
}

// ======================= device scratch ====================================
__device__ __align__(256) __nv_bfloat16 g_xhi[(size_t)N_TOK * DIM];
__device__ __align__(256) __nv_bfloat16 g_xlo[(size_t)N_TOK * DIM];
__device__ __align__(256) __nv_bfloat16 g_ehi[(size_t)KEMB * DIM];
__device__ __align__(256) __nv_bfloat16 g_elo[(size_t)KEMB * DIM];
__device__ float g_enorm[KEMB];
__device__ int   g_idx[N_TOK];
__device__ float g_tokloss[N_TOK / 4];
__device__ int   g_hist[KEMB];
__device__ int   g_nrcnt;
__device__ int   g_rlist[N_TOK];

// ======================= kernel 0: X split-bf16 conversion (half grid) =====
__global__ __launch_bounds__(256)
void convert_kernel(const float* __restrict__ X, int off4) {
    size_t i = (size_t)off4 + (size_t)blockIdx.x * 256 + threadIdx.x;
    float4 v = ((const float4*)X)[i];
    union { __nv_bfloat16 h[4]; uint2 u; } hi, lo;
    hi.h[0] = __float2bfloat16(v.x); lo.h[0] = __float2bfloat16(v.x - __bfloat162float(hi.h[0]));
    hi.h[1] = __float2bfloat16(v.y); lo.h[1] = __float2bfloat16(v.y - __bfloat162float(hi.h[1]));
    hi.h[2] = __float2bfloat16(v.z); lo.h[2] = __float2bfloat16(v.z - __bfloat162float(hi.h[2]));
    hi.h[3] = __float2bfloat16(v.w); lo.h[3] = __float2bfloat16(v.w - __bfloat162float(hi.h[3]));
    ((uint2*)g_xhi)[i] = hi.u;
    ((uint2*)g_xlo)[i] = lo.u;
}

// ======================= kernel 1: ||e||^2 + E->bf16 hi/lo + zeroing =======
__global__ __launch_bounds__(256)
void enorm_kernel(const float* __restrict__ E) {
    int warp = threadIdx.x >> 5;
    int lane = threadIdx.x & 31;
    int row  = blockIdx.x * 8 + warp;

    const float* r = E + (size_t)row * DIM;
    float s = 0.f;
    #pragma unroll
    for (int i = 0; i < DIM / 32; i++) {
        float v = r[lane + i * 32];
        __nv_bfloat16 h = __float2bfloat16(v);
        g_ehi[(size_t)row * DIM + lane + i * 32] = h;
        g_elo[(size_t)row * DIM + lane + i * 32] =
            __float2bfloat16(v - __bfloat162float(h));
        s = fmaf(v, v, s);
    }
    #pragma unroll
    for (int o = 16; o > 0; o >>= 1) s += __shfl_xor_sync(0xFFFFFFFFu, s, o);
    if (lane == 0) g_enorm[row] = s;

    int gid = blockIdx.x * blockDim.x + threadIdx.x;
    if (gid < KEMB) g_hist[gid] = 0;
    if (gid == 0)   g_nrcnt = 0;
}

// ======================= kernel 2: mma.sync distances + argmin =============
// 64 tokens / CTA (1024 CTAs), 2 CTAs/SM.  A (xhi,xlo) resident.
// B streamed in 128cw x 32k chunks of (ehi,elo), double buffered.
// 8 warps: EACH warp covers all 64 rows (mi 0..3) x 16 cols (wn = wid).
// Per k-step/warp: 8 A-ldm + 2 B-ldm + 24 HMMA  (ratio 0.42 vs 0.67 before).
#define A_STRIDE 264                        // bf16 -> 528 B (33*16)
#define A_SLAB   (64 * A_STRIDE * 2)        // 33792 B
#define B_STRIDE 40                         // bf16 -> 80 B (5*16)
#define B_CHUNK  (128 * B_STRIDE * 2)       // 10240 B (one of ehi|elo)
#define B_PAIR   (2 * B_CHUNK)              // 20480 B per buffer
#define OFF_EN   0
#define OFF_A    4096
#define OFF_B    (OFF_A + 2 * A_SLAB)       // 71680
#define GSMEM    (OFF_B + 2 * B_PAIR)       // 112640  (2 CTAs/SM)

__global__ __launch_bounds__(256, 2)
void vq_mma_kernel(const float* __restrict__ X) {
    extern __shared__ char smem[];
    const uint32_t sb = smem_to_u32(smem);
    const int tid  = threadIdx.x;
    const int lane = tid & 31;
    const int wid  = tid >> 5;
    const int g    = lane >> 2;
    const int t    = lane & 3;
    const int wn   = wid;                 // 8 warps x 16 cols = 128 cols
    const int ncol0 = wn * 16;
    const int brow  = blockIdx.x * 64;

    float* s_en = (float*)(smem + OFF_EN);
    #pragma unroll
    for (int i = 0; i < 4; i++) s_en[tid + i * 256] = g_enorm[tid + i * 256];

    // ---- prologue: resident A (hi+lo) + B chunk 0 ----
    for (int it = tid; it < 4096; it += 256) {
        int slab = it >> 11, rem = it & 2047;
        int row = rem >> 5, j = rem & 31;
        const __nv_bfloat16* src = ((slab == 0) ? g_xhi : g_xlo)
            + (size_t)(brow + row) * DIM + j * 8;
        CP_ASYNC16(sb + OFF_A + slab * A_SLAB + row * (A_STRIDE * 2) + j * 16, src);
    }
    for (int it = tid; it < 1024; it += 256) {
        int half = it >> 9, rem = it & 511;
        int n = rem >> 2, j = rem & 3;
        const __nv_bfloat16* src = ((half == 0) ? g_ehi : g_elo)
            + (size_t)n * DIM + j * 8;
        CP_ASYNC16(sb + OFF_B + half * B_CHUNK + n * (B_STRIDE * 2) + j * 16, src);
    }
    CP_COMMIT();

    // ---- precomputed ldmatrix addresses ----
    const int a_row  = (lane & 7) + ((lane >> 3) & 1) * 8;   // + mi*16
    const int a_koff = (lane >> 4) * 8;
    uint32_t aAddr[4][2];
    #pragma unroll
    for (int mi = 0; mi < 4; mi++)
        #pragma unroll
        for (int hl = 0; hl < 2; hl++)
            aAddr[mi][hl] = sb + OFF_A + hl * A_SLAB
                + (a_row + mi * 16) * (A_STRIDE * 2) + a_koff * 2;
    const int b_n    = ncol0 + ((lane >> 3) & 1) * 8 + (lane & 7);
    const int b_koff = (lane >> 4) * 8;
    const uint32_t bAddr = sb + OFF_B + b_n * (B_STRIDE * 2) + b_koff * 2;

    float acc[4][2][4];
    #pragma unroll
    for (int mi = 0; mi < 4; mi++)
        #pragma unroll
        for (int nf = 0; nf < 2; nf++)
            #pragma unroll
            for (int c = 0; c < 4; c++) acc[mi][nf][c] = 0.f;

    float best[8], sec[8];
    int   bidv[8];
    #pragma unroll
    for (int r = 0; r < 8; r++) { best[r] = 3.0e38f; sec[r] = 3.0e38f; bidv[r] = 0; }

    for (int i = 0; i < 64; i++) {
        const int cb = i >> 3, ch = i & 7, buf = i & 1;

        if (i > 0) __syncthreads();
        if (i + 1 < 64) {
            const int cb2 = (i + 1) >> 3, ch2 = (i + 1) & 7, nb = (i + 1) & 1;
            for (int it = tid; it < 1024; it += 256) {
                int half = it >> 9, rem = it & 511;
                int n = rem >> 2, j = rem & 3;
                const __nv_bfloat16* src = ((half == 0) ? g_ehi : g_elo)
                    + (size_t)(cb2 * 128 + n) * DIM + ch2 * 32 + j * 8;
                CP_ASYNC16(sb + OFF_B + nb * B_PAIR + half * B_CHUNK
                           + n * (B_STRIDE * 2) + j * 16, src);
            }
            CP_COMMIT();
            CP_WAIT(1);
        } else {
            CP_WAIT(0);
        }
        __syncthreads();

        // ---- compute chunk i : 2 k-steps of 16 ----
        const uint32_t aK   = (uint32_t)(ch * 32) * 2;
        const uint32_t bBuf = (uint32_t)(buf * B_PAIR);
        #pragma unroll
        for (int step = 0; step < 2; step++) {
            uint32_t bh[4], bl[4];
            ldm_x4(bh, bAddr + bBuf + step * 32);
            ldm_x4(bl, bAddr + bBuf + B_CHUNK + step * 32);
            #pragma unroll
            for (int mi = 0; mi < 4; mi++) {
                uint32_t ahi[4], alo[4];
                ldm_x4(ahi, aAddr[mi][0] + aK + step * 32);
                ldm_x4(alo, aAddr[mi][1] + aK + step * 32);
                // k-half pairing: (b[0],b[2]) n-block 0, (b[1],b[3]) n-block 1
                mma_bf16(acc[mi][0], ahi, bh[0], bh[2]);
                mma_bf16(acc[mi][0], alo, bh[0], bh[2]);
                mma_bf16(acc[mi][0], ahi, bl[0], bl[2]);
                mma_bf16(acc[mi][1], ahi, bh[1], bh[3]);
                mma_bf16(acc[mi][1], alo, bh[1], bh[3]);
                mma_bf16(acc[mi][1], ahi, bl[1], bl[3]);
            }
        }

        if (ch == 7) {   // codeword tile done: fold into running argmin
            const int cbase = cb * 128 + ncol0;
            #pragma unroll
            for (int mi = 0; mi < 4; mi++) {
                #pragma unroll
                for (int nf = 0; nf < 2; nf++) {
                    const int colb = cbase + nf * 8 + 2 * t;
                    #pragma unroll
                    for (int h = 0; h < 2; h++) {
                        const int tr = mi * 2 + h;
                        float d0 = fmaf(-2.f, acc[mi][nf][h * 2 + 0], s_en[colb]);
                        float d1 = fmaf(-2.f, acc[mi][nf][h * 2 + 1], s_en[colb + 1]);
                        if (d0 < best[tr]) { sec[tr] = best[tr]; best[tr] = d0; bidv[tr] = colb; }
                        else if (d0 < sec[tr]) sec[tr] = d0;
                        if (d1 < best[tr]) { sec[tr] = best[tr]; best[tr] = d1; bidv[tr] = colb + 1; }
                        else if (d1 < sec[tr]) sec[tr] = d1;
                        acc[mi][nf][h * 2 + 0] = 0.f;
                        acc[mi][nf][h * 2 + 1] = 0.f;
                    }
                }
            }
        }
    }

    // ---- cross-thread merge (overlay scratch on B region) ----
    __syncthreads();
    float* mb = (float*)(smem + OFF_B);   // [row 64][slot 32] {best, sec, idx}
    const int slot = wn * 4 + t;          // 32 slots per row
    #pragma unroll
    for (int mi = 0; mi < 4; mi++)
        #pragma unroll
        for (int h = 0; h < 2; h++) {
            int row = mi * 16 + h * 8 + g;
            int tr  = mi * 2 + h;
            int o   = (row * 32 + slot) * 3;
            mb[o] = best[tr]; mb[o + 1] = sec[tr]; ((int*)mb)[o + 2] = bidv[tr];
        }
    __syncthreads();

    if (tid < 64) {
        float gb = 3.0e38f; int gi = 0;
        #pragma unroll
        for (int s = 0; s < 32; s++) {
            int o = (tid * 32 + s) * 3;
            float v = mb[o]; int ix = ((int*)mb)[o + 2];
            if (v < gb || (v == gb && ix < gi)) { gb = v; gi = ix; }
        }
        float gs = 3.0e38f;
        #pragma unroll
        for (int s = 0; s < 32; s++) {
            int o = (tid * 32 + s) * 3;
            float v = mb[o], v2 = mb[o + 1]; int ix = ((int*)mb)[o + 2];
            float cand = (ix == gi) ? v2 : v;
            if (cand < gs) gs = cand;
        }
        int token = brow + tid;
        g_idx[token] = gi;
        if (gs - gb < MARGIN) {
            int p = atomicAdd(&g_nrcnt, 1);
            g_rlist[p] = token;
        }
    }
}

// ======================= kernel 3: exact fp32 recheck (1 token/block) ======
__global__ __launch_bounds__(256)
void recheck_kernel(const float* __restrict__ X, const float* __restrict__ E) {
    __shared__ float xs[DIM];
    __shared__ float sv[256];
    __shared__ int   si[256];
    const int tid = threadIdx.x;
    const int cnt_total = g_nrcnt;

    for (int wi = blockIdx.x; wi < cnt_total; wi += gridDim.x) {
        __syncthreads();
        const int tk = g_rlist[wi];
        xs[tid] = X[(size_t)tk * DIM + tid];
        __syncthreads();

        float acc[4] = {0.f, 0.f, 0.f, 0.f};
        const float4* e0 = (const float4*)(E + (size_t)(tid * 4 + 0) * DIM);
        const float4* e1 = (const float4*)(E + (size_t)(tid * 4 + 1) * DIM);
        const float4* e2 = (const float4*)(E + (size_t)(tid * 4 + 2) * DIM);
        const float4* e3 = (const float4*)(E + (size_t)(tid * 4 + 3) * DIM);

        #pragma unroll 8
        for (int j = 0; j < DIM / 4; j++) {
            float4 xv = *(const float4*)&xs[j * 4];   // broadcast
            float4 ev;
            ev = e0[j];
            acc[0] = fmaf(xv.x, ev.x, fmaf(xv.y, ev.y, fmaf(xv.z, ev.z, fmaf(xv.w, ev.w, acc[0]))));
            ev = e1[j];
            acc[1] = fmaf(xv.x, ev.x, fmaf(xv.y, ev.y, fmaf(xv.z, ev.z, fmaf(xv.w, ev.w, acc[1]))));
            ev = e2[j];
            acc[2] = fmaf(xv.x, ev.x, fmaf(xv.y, ev.y, fmaf(xv.z, ev.z, fmaf(xv.w, ev.w, acc[2]))));
            ev = e3[j];
            acc[3] = fmaf(xv.x, ev.x, fmaf(xv.y, ev.y, fmaf(xv.z, ev.z, fmaf(xv.w, ev.w, acc[3]))));
        }

        float bv = 3.0e38f; int bi = 0;
        #pragma unroll
        for (int c = 0; c < 4; c++) {   // ascending k -> strict < keeps first
            float d = fmaf(-2.f, acc[c], g_enorm[tid * 4 + c]);
            if (d < bv) { bv = d; bi = tid * 4 + c; }
        }

        sv[tid] = bv; si[tid] = bi;
        __syncthreads();
        for (int st = 128; st > 0; st >>= 1) {
            if (tid < st) {
                float v2 = sv[tid + st]; int i2 = si[tid + st];
                if (v2 < sv[tid] || (v2 == sv[tid] && i2 < si[tid])) {
                    sv[tid] = v2; si[tid] = i2;
                }
            }
            __syncthreads();
        }
        if (tid == 0) g_idx[tk] = si[0];
    }
}

// ======================= kernel 4: fused epilogue (4 tokens/block) =========
__global__ __launch_bounds__(256)
void vq_epilogue_kernel(const float* __restrict__ X, const float* __restrict__ E,
                        float* __restrict__ out_q, float* __restrict__ out_idx,
                        float* __restrict__ out_enc) {
    const int tid  = threadIdx.x;
    const int base = blockIdx.x * 4;

    float sq = 0.f;
    #pragma unroll
    for (int tk = 0; tk < 4; tk++) {
        const int t   = base + tk;
        const int idx = g_idx[t];

        if (tid == 0) {
            atomicAdd(&g_hist[idx], 1);
            out_idx[t] = (float)idx;
        }

        float q = E[(size_t)idx * DIM + tid];
        float x = X[(size_t)t   * DIM + tid];
        out_q[(size_t)t * DIM + tid] = q;
        float d = q - x;
        sq = fmaf(d, d, sq);

        float* erow = out_enc + (size_t)t * KEMB;
        if (tid < 255) {
            const int sbase = 2 + tid * 4;
            float4 v;
            v.x = (idx == sbase)     ? 1.f : 0.f;
            v.y = (idx == sbase + 1) ? 1.f : 0.f;
            v.z = (idx == sbase + 2) ? 1.f : 0.f;
            v.w = (idx == sbase + 3) ? 1.f : 0.f;
            *(float4*)(erow + sbase) = v;
        } else {
            erow[0]    = (idx == 0)    ? 1.f : 0.f;
            erow[1]    = (idx == 1)    ? 1.f : 0.f;
            erow[1022] = (idx == 1022) ? 1.f : 0.f;
            erow[1023] = (idx == 1023) ? 1.f : 0.f;
        }
    }

    #pragma unroll
    for (int o = 16; o > 0; o >>= 1) sq += __shfl_xor_sync(0xFFFFFFFFu, sq, o);
    __shared__ float ws[8];
    if ((tid & 31) == 0) ws[tid >> 5] = sq;
    __syncthreads();
    if (tid == 0) {
        float s = 0.f;
        #pragma unroll
        for (int i = 0; i < 8; i++) s += ws[i];
        g_tokloss[blockIdx.x] = s;
    }
}

// ======================= kernel 5: finalize ================================
__global__ __launch_bounds__(256)
void vq_finalize_kernel(float* __restrict__ out_loss, float* __restrict__ out_perp) {
    __shared__ double sm[256];
    const int tid = threadIdx.x;

    double s = 0.0;
    for (int i = tid; i < N_TOK / 4; i += 256) s += (double)g_tokloss[i];
    sm[tid] = s;
    __syncthreads();
    for (int st = 128; st > 0; st >>= 1) {
        if (tid < st) sm[tid] += sm[tid + st];
        __syncthreads();
    }
    if (tid == 0)
        out_loss[0] = (float)(0.25 * sm[0] / ((double)N_TOK * (double)DIM));
    __syncthreads();

    double p = 0.0;
    for (int i = tid; i < KEMB; i += 256) {
        double pk = (double)g_hist[i] / (double)N_TOK;
        p += pk * log(pk + 1e-10);
    }
    sm[tid] = p;
    __syncthreads();
    for (int st = 128; st > 0; st >>= 1) {
        if (tid < st) sm[tid] += sm[tid + st];
        __syncthreads();
    }
    if (tid == 0)
        out_perp[0] = (float)exp(-sm[0]);
}

// ---------------------------------------------------------------------------
extern "C" void kernel_launch(void* const* d_in, const int* in_sizes, int n_in,
                              void* d_out, int out_size) {
    const float* X = (const float*)d_in[0];
    const float* E = (const float*)d_in[1];
    if (n_in >= 2 && in_sizes[0] == KEMB * DIM && in_sizes[1] == N_TOK * DIM) {
        const float* tmp = X; X = E; E = tmp;
    }

    float* out      = (float*)d_out;
    float* out_loss = out;
    float* out_q    = out + 1;
    float* out_idx  = out + 1 + (size_t)N_TOK * DIM;
    float* out_perp = out_idx + N_TOK;
    float* out_enc  = out_perp + 1;

    cudaFuncSetAttribute(vq_mma_kernel,
                         cudaFuncAttributeMaxDynamicSharedMemorySize, GSMEM);

    const int CONV_BLOCKS = N_TOK * DIM / 4 / 256;   // 16384 total
    convert_kernel    <<<CONV_BLOCKS / 2, 256>>>(X, 0);
    convert_kernel    <<<CONV_BLOCKS / 2, 256>>>(X, CONV_BLOCKS / 2 * 256);
    enorm_kernel      <<<128, 256>>>(E);
    vq_mma_kernel     <<<N_TOK / 64, 256, GSMEM>>>(X);   // launch #4 -> profiled
    recheck_kernel    <<<2048, 256>>>(X, E);
    vq_epilogue_kernel<<<N_TOK / 4, 256>>>(X, E, out_q, out_idx, out_enc);
    vq_finalize_kernel<<<1, 256>>>(out_loss, out_perp);
}

// round 12
// speedup vs baseline: 1.1266x; 1.1266x over previous
#include <cuda_runtime.h>
#include <cuda_fp16.h>
#include <math.h>
#include <stdint.h>

#define N_TOK 65536
#define DIM   256
#define KEMB  1024
#define MARGIN 0.12f

// ======================= helpers ===========================================
__device__ __forceinline__ uint32_t smem_to_u32(const void* p) {
    uint32_t a;
    asm("{ .reg .u64 t; cvta.to.shared.u64 t, %1; cvt.u32.u64 %0, t; }"
        : "=r"(a) : "l"(p));
    return a;
}
#define CP_ASYNC16(dst, src) \
    asm volatile("cp.async.cg.shared.global [%0], [%1], 16;" :: "r"(dst), "l"(src))
#define CP_COMMIT() asm volatile("cp.async.commit_group;" ::: "memory")
#define CP_WAIT(n)  asm volatile("cp.async.wait_group %0;" :: "n"(n) : "memory")

__device__ __forceinline__ void ldm_x4(uint32_t* r, uint32_t addr) {
    asm volatile("ldmatrix.sync.aligned.m8n8.x4.shared.b16 {%0,%1,%2,%3}, [%4];"
        : "=r"(r[0]), "=r"(r[1]), "=r"(r[2]), "=r"(r[3]) : "r"(addr));
}
__device__ __forceinline__ void mma_f16(float* c, const uint32_t* a,
                                        uint32_t b0, uint32_t b1) {
    asm volatile(
        "mma.sync.aligned.m16n8k16.row.col.f32.f16.f16.f32 "
        "{%0,%1,%2,%3}, {%4,%5,%6,%7}, {%8,%9}, {%0,%1,%2,%3};"
        : "+f"(c[0]), "+f"(c[1]), "+f"(c[2]), "+f"(c[3])
        : "r"(a[0]), "r"(a[1]), "r"(a[2]), "r"(a[3]), "r"(b0), "r"(b1));
}

// ======================= device scratch ====================================
__device__ __align__(256) __half g_xh[(size_t)N_TOK * DIM];
__device__ __align__(256) __half g_eh[(size_t)KEMB * DIM];
__device__ float g_enorm[KEMB];
__device__ int   g_idx[N_TOK];
__device__ float g_tokloss[N_TOK / 4];
__device__ int   g_hist[KEMB];
__device__ int   g_nrcnt;
__device__ int   g_rlist[N_TOK];

// ======================= kernel 0: X -> fp16 (half grid x2) ================
__global__ __launch_bounds__(256)
void convert_kernel(const float* __restrict__ X, int off4) {
    size_t i = (size_t)off4 + (size_t)blockIdx.x * 256 + threadIdx.x;
    float4 v = ((const float4*)X)[i];
    union { __half h[4]; uint2 u; } o;
    o.h[0] = __float2half_rn(v.x);
    o.h[1] = __float2half_rn(v.y);
    o.h[2] = __float2half_rn(v.z);
    o.h[3] = __float2half_rn(v.w);
    ((uint2*)g_xh)[i] = o.u;
}

// ======================= kernel 1: ||e||^2 + E->fp16 + zeroing =============
__global__ __launch_bounds__(256)
void enorm_kernel(const float* __restrict__ E) {
    int warp = threadIdx.x >> 5;
    int lane = threadIdx.x & 31;
    int row  = blockIdx.x * 8 + warp;

    const float* r = E + (size_t)row * DIM;
    float s = 0.f;
    #pragma unroll
    for (int i = 0; i < DIM / 32; i++) {
        float v = r[lane + i * 32];
        g_eh[(size_t)row * DIM + lane + i * 32] = __float2half_rn(v);
        s = fmaf(v, v, s);
    }
    #pragma unroll
    for (int o = 16; o > 0; o >>= 1) s += __shfl_xor_sync(0xFFFFFFFFu, s, o);
    if (lane == 0) g_enorm[row] = s;

    int gid = blockIdx.x * blockDim.x + threadIdx.x;
    if (gid < KEMB) g_hist[gid] = 0;
    if (gid == 0)   g_nrcnt = 0;
}

// ======================= kernel 2: fp16 mma distances + argmin =============
// 64 tokens / CTA (1024 CTAs), 2 CTAs/SM.  A = xh resident (33.8KB).
// B = eh streamed in 256cw x 64k chunks, double buffered (72KB).
// 8 warps: each covers all 64 rows x 32 cols (wn = wid).
// ONE fp16 product: d = ||e||^2 - 2*(xh . eh); err sigma ~6e-3, MARGIN=0.12
// (~13 sigma on a pair difference) flags every at-risk token for exact recheck.
#define A_ROWB   528                        // 264 halves * 2 B  (33*16)
#define A_SLAB   (64 * A_ROWB)              // 33792 B
#define B_ROWB   144                        // 72 halves * 2 B   (9*16)
#define B_CHUNK  (256 * B_ROWB)             // 36864 B
#define OFF_EN   0
#define OFF_A    4096
#define OFF_B    (OFF_A + A_SLAB)           // 37888
#define GSMEM    (OFF_B + 2 * B_CHUNK)      // 111616  (2 CTAs/SM)

__global__ __launch_bounds__(256, 2)
void vq_mma_kernel(const float* __restrict__ X) {
    extern __shared__ char smem[];
    const uint32_t sb = smem_to_u32(smem);
    const int tid  = threadIdx.x;
    const int lane = tid & 31;
    const int wid  = tid >> 5;
    const int g    = lane >> 2;
    const int t    = lane & 3;
    const int ncol0 = wid * 32;              // 8 warps x 32 cols = 256 cols
    const int brow  = blockIdx.x * 64;

    float* s_en = (float*)(smem + OFF_EN);
    #pragma unroll
    for (int i = 0; i < 4; i++) s_en[tid + i * 256] = g_enorm[tid + i * 256];

    // ---- per-thread fill slots (strength-reduced addressing) ----
    const int fn = tid >> 3;                 // row slot 0..31 (+s*32)
    const int fj = tid & 7;                  // 16B slot in row
    const __half* bsrc0 = g_eh + (size_t)fn * DIM + fj * 8;
    const uint32_t bdst0 = sb + OFF_B + fn * B_ROWB + fj * 16;

    // ---- prologue: resident A + B chunk 0 ----
    for (int it = tid; it < 2048; it += 256) {
        int row = it >> 5, j = it & 31;
        CP_ASYNC16(sb + OFF_A + row * A_ROWB + j * 16,
                   g_xh + (size_t)(brow + row) * DIM + j * 8);
    }
    {
        const __half* s = bsrc0;
        uint32_t d = bdst0;
        #pragma unroll
        for (int ss = 0; ss < 8; ss++) {
            CP_ASYNC16(d, s);
            s += 32 * DIM; d += 32 * B_ROWB;
        }
    }
    CP_COMMIT();

    // ---- ldmatrix addresses ----
    const int a_row  = (lane & 7) + ((lane >> 3) & 1) * 8;   // + mi*16
    const int a_kb   = (lane >> 4) * 16;                     // k-half bytes
    uint32_t aAddr[4];
    #pragma unroll
    for (int mi = 0; mi < 4; mi++)
        aAddr[mi] = sb + OFF_A + (a_row + mi * 16) * A_ROWB + a_kb;
    const int b_n = ncol0 + ((lane >> 3) & 1) * 8 + (lane & 7);  // + nfp*16
    uint32_t bAddr[2];
    #pragma unroll
    for (int nfp = 0; nfp < 2; nfp++)
        bAddr[nfp] = sb + OFF_B + (b_n + nfp * 16) * B_ROWB + (lane >> 4) * 16;

    float acc[4][4][4];
    #pragma unroll
    for (int mi = 0; mi < 4; mi++)
        #pragma unroll
        for (int nf = 0; nf < 4; nf++)
            #pragma unroll
            for (int c = 0; c < 4; c++) acc[mi][nf][c] = 0.f;

    float best[8], sec[8];
    int   bidv[8];
    #pragma unroll
    for (int r = 0; r < 8; r++) { best[r] = 3.0e38f; sec[r] = 3.0e38f; bidv[r] = 0; }

    for (int i = 0; i < 16; i++) {           // 4 cb-tiles x 4 k-chunks
        const int cb = i >> 2, ch = i & 3, buf = i & 1;

        if (i > 0) __syncthreads();
        if (i + 1 < 16) {
            const int cb2 = (i + 1) >> 2, ch2 = (i + 1) & 3, nb = (i + 1) & 1;
            const __half* s = bsrc0 + (size_t)cb2 * 256 * DIM + ch2 * 64;
            uint32_t d = bdst0 + nb * B_CHUNK;
            #pragma unroll
            for (int ss = 0; ss < 8; ss++) {
                CP_ASYNC16(d, s);
                s += 32 * DIM; d += 32 * B_ROWB;
            }
            CP_COMMIT();
            CP_WAIT(1);
        } else {
            CP_WAIT(0);
        }
        __syncthreads();

        // ---- compute chunk i : 4 k-steps of 16 ----
        const uint32_t aK   = (uint32_t)(ch * 128);   // 64 halves = 128 B
        const uint32_t bBuf = (uint32_t)(buf * B_CHUNK);
        #pragma unroll
        for (int step = 0; step < 4; step++) {
            uint32_t a[4][4];
            #pragma unroll
            for (int mi = 0; mi < 4; mi++)
                ldm_x4(a[mi], aAddr[mi] + aK + step * 32);
            #pragma unroll
            for (int nfp = 0; nfp < 2; nfp++) {
                uint32_t b[4];
                ldm_x4(b, bAddr[nfp] + bBuf + step * 32);
                // k-half pairing: (b[0],b[2]) n-blk 0, (b[1],b[3]) n-blk 1
                #pragma unroll
                for (int mi = 0; mi < 4; mi++) {
                    mma_f16(acc[mi][nfp * 2],     a[mi], b[0], b[2]);
                    mma_f16(acc[mi][nfp * 2 + 1], a[mi], b[1], b[3]);
                }
            }
        }

        if (ch == 3) {   // 256-col tile done: fold into running argmin
            const int cbase = cb * 256 + ncol0;
            #pragma unroll
            for (int mi = 0; mi < 4; mi++) {
                #pragma unroll
                for (int nf = 0; nf < 4; nf++) {
                    const int colb = cbase + nf * 8 + 2 * t;
                    #pragma unroll
                    for (int h = 0; h < 2; h++) {
                        const int tr = mi * 2 + h;
                        float d0 = fmaf(-2.f, acc[mi][nf][h * 2 + 0], s_en[colb]);
                        float d1 = fmaf(-2.f, acc[mi][nf][h * 2 + 1], s_en[colb + 1]);
                        if (d0 < best[tr]) { sec[tr] = best[tr]; best[tr] = d0; bidv[tr] = colb; }
                        else if (d0 < sec[tr]) sec[tr] = d0;
                        if (d1 < best[tr]) { sec[tr] = best[tr]; best[tr] = d1; bidv[tr] = colb + 1; }
                        else if (d1 < sec[tr]) sec[tr] = d1;
                        acc[mi][nf][h * 2 + 0] = 0.f;
                        acc[mi][nf][h * 2 + 1] = 0.f;
                    }
                }
            }
        }
    }

    // ---- cross-thread merge (overlay scratch on B region) ----
    __syncthreads();
    float* mb = (float*)(smem + OFF_B);   // [row 64][slot 32] {best, sec, idx}
    const int slot = wid * 4 + t;
    #pragma unroll
    for (int mi = 0; mi < 4; mi++)
        #pragma unroll
        for (int h = 0; h < 2; h++) {
            int row = mi * 16 + h * 8 + g;
            int tr  = mi * 2 + h;
            int o   = (row * 32 + slot) * 3;
            mb[o] = best[tr]; mb[o + 1] = sec[tr]; ((int*)mb)[o + 2] = bidv[tr];
        }
    __syncthreads();

    if (tid < 64) {
        float gb = 3.0e38f; int gi = 0;
        #pragma unroll
        for (int s = 0; s < 32; s++) {
            int o = (tid * 32 + s) * 3;
            float v = mb[o]; int ix = ((int*)mb)[o + 2];
            if (v < gb || (v == gb && ix < gi)) { gb = v; gi = ix; }
        }
        float gs = 3.0e38f;
        #pragma unroll
        for (int s = 0; s < 32; s++) {
            int o = (tid * 32 + s) * 3;
            float v = mb[o], v2 = mb[o + 1]; int ix = ((int*)mb)[o + 2];
            float cand = (ix == gi) ? v2 : v;
            if (cand < gs) gs = cand;
        }
        int token = brow + tid;
        g_idx[token] = gi;
        if (gs - gb < MARGIN) {
            int p = atomicAdd(&g_nrcnt, 1);
            g_rlist[p] = token;
        }
    }
}

// ======================= kernel 3: exact fp32 recheck (1 token/block) ======
__global__ __launch_bounds__(256)
void recheck_kernel(const float* __restrict__ X, const float* __restrict__ E) {
    __shared__ float xs[DIM];
    __shared__ float sv[256];
    __shared__ int   si[256];
    const int tid = threadIdx.x;
    const int cnt_total = g_nrcnt;

    for (int wi = blockIdx.x; wi < cnt_total; wi += gridDim.x) {
        __syncthreads();
        const int tk = g_rlist[wi];
        xs[tid] = X[(size_t)tk * DIM + tid];
        __syncthreads();

        float acc[4] = {0.f, 0.f, 0.f, 0.f};
        const float4* e0 = (const float4*)(E + (size_t)(tid * 4 + 0) * DIM);
        const float4* e1 = (const float4*)(E + (size_t)(tid * 4 + 1) * DIM);
        const float4* e2 = (const float4*)(E + (size_t)(tid * 4 + 2) * DIM);
        const float4* e3 = (const float4*)(E + (size_t)(tid * 4 + 3) * DIM);

        #pragma unroll 8
        for (int j = 0; j < DIM / 4; j++) {
            float4 xv = *(const float4*)&xs[j * 4];
            float4 ev;
            ev = e0[j];
            acc[0] = fmaf(xv.x, ev.x, fmaf(xv.y, ev.y, fmaf(xv.z, ev.z, fmaf(xv.w, ev.w, acc[0]))));
            ev = e1[j];
            acc[1] = fmaf(xv.x, ev.x, fmaf(xv.y, ev.y, fmaf(xv.z, ev.z, fmaf(xv.w, ev.w, acc[1]))));
            ev = e2[j];
            acc[2] = fmaf(xv.x, ev.x, fmaf(xv.y, ev.y, fmaf(xv.z, ev.z, fmaf(xv.w, ev.w, acc[2]))));
            ev = e3[j];
            acc[3] = fmaf(xv.x, ev.x, fmaf(xv.y, ev.y, fmaf(xv.z, ev.z, fmaf(xv.w, ev.w, acc[3]))));
        }

        float bv = 3.0e38f; int bi = 0;
        #pragma unroll
        for (int c = 0; c < 4; c++) {
            float d = fmaf(-2.f, acc[c], g_enorm[tid * 4 + c]);
            if (d < bv) { bv = d; bi = tid * 4 + c; }
        }

        sv[tid] = bv; si[tid] = bi;
        __syncthreads();
        for (int st = 128; st > 0; st >>= 1) {
            if (tid < st) {
                float v2 = sv[tid + st]; int i2 = si[tid + st];
                if (v2 < sv[tid] || (v2 == sv[tid] && i2 < si[tid])) {
                    sv[tid] = v2; si[tid] = i2;
                }
            }
            __syncthreads();
        }
        if (tid == 0) g_idx[tk] = si[0];
    }
}

// ======================= kernel 4: fused epilogue (4 tokens/block) =========
__global__ __launch_bounds__(256)
void vq_epilogue_kernel(const float* __restrict__ X, const float* __restrict__ E,
                        float* __restrict__ out_q, float* __restrict__ out_idx,
                        float* __restrict__ out_enc) {
    const int tid  = threadIdx.x;
    const int base = blockIdx.x * 4;

    float sq = 0.f;
    #pragma unroll
    for (int tk = 0; tk < 4; tk++) {
        const int t   = base + tk;
        const int idx = g_idx[t];

        if (tid == 0) {
            atomicAdd(&g_hist[idx], 1);
            out_idx[t] = (float)idx;
        }

        float q = E[(size_t)idx * DIM + tid];
        float x = X[(size_t)t   * DIM + tid];
        out_q[(size_t)t * DIM + tid] = q;
        float d = q - x;
        sq = fmaf(d, d, sq);

        float* erow = out_enc + (size_t)t * KEMB;
        if (tid < 255) {
            const int sbase = 2 + tid * 4;
            float4 v;
            v.x = (idx == sbase)     ? 1.f : 0.f;
            v.y = (idx == sbase + 1) ? 1.f : 0.f;
            v.z = (idx == sbase + 2) ? 1.f : 0.f;
            v.w = (idx == sbase + 3) ? 1.f : 0.f;
            *(float4*)(erow + sbase) = v;
        } else {
            erow[0]    = (idx == 0)    ? 1.f : 0.f;
            erow[1]    = (idx == 1)    ? 1.f : 0.f;
            erow[1022] = (idx == 1022) ? 1.f : 0.f;
            erow[1023] = (idx == 1023) ? 1.f : 0.f;
        }
    }

    #pragma unroll
    for (int o = 16; o > 0; o >>= 1) sq += __shfl_xor_sync(0xFFFFFFFFu, sq, o);
    __shared__ float ws[8];
    if ((tid & 31) == 0) ws[tid >> 5] = sq;
    __syncthreads();
    if (tid == 0) {
        float s = 0.f;
        #pragma unroll
        for (int i = 0; i < 8; i++) s += ws[i];
        g_tokloss[blockIdx.x] = s;
    }
}

// ======================= kernel 5: finalize ================================
__global__ __launch_bounds__(256)
void vq_finalize_kernel(float* __restrict__ out_loss, float* __restrict__ out_perp) {
    __shared__ double sm[256];
    const int tid = threadIdx.x;

    double s = 0.0;
    for (int i = tid; i < N_TOK / 4; i += 256) s += (double)g_tokloss[i];
    sm[tid] = s;
    __syncthreads();
    for (int st = 128; st > 0; st >>= 1) {
        if (tid < st) sm[tid] += sm[tid + st];
        __syncthreads();
    }
    if (tid == 0)
        out_loss[0] = (float)(0.25 * sm[0] / ((double)N_TOK * (double)DIM));
    __syncthreads();

    double p = 0.0;
    for (int i = tid; i < KEMB; i += 256) {
        double pk = (double)g_hist[i] / (double)N_TOK;
        p += pk * log(pk + 1e-10);
    }
    sm[tid] = p;
    __syncthreads();
    for (int st = 128; st > 0; st >>= 1) {
        if (tid < st) sm[tid] += sm[tid + st];
        __syncthreads();
    }
    if (tid == 0)
        out_perp[0] = (float)exp(-sm[0]);
}

// ---------------------------------------------------------------------------
extern "C" void kernel_launch(void* const* d_in, const int* in_sizes, int n_in,
                              void* d_out, int out_size) {
    const float* X = (const float*)d_in[0];
    const float* E = (const float*)d_in[1];
    if (n_in >= 2 && in_sizes[0] == KEMB * DIM && in_sizes[1] == N_TOK * DIM) {
        const float* tmp = X; X = E; E = tmp;
    }

    float* out      = (float*)d_out;
    float* out_loss = out;
    float* out_q    = out + 1;
    float* out_idx  = out + 1 + (size_t)N_TOK * DIM;
    float* out_perp = out_idx + N_TOK;
    float* out_enc  = out_perp + 1;

    cudaFuncSetAttribute(vq_mma_kernel,
                         cudaFuncAttributeMaxDynamicSharedMemorySize, GSMEM);

    const int CONV_BLOCKS = N_TOK * DIM / 4 / 256;   // 16384 total
    convert_kernel    <<<CONV_BLOCKS / 2, 256>>>(X, 0);
    convert_kernel    <<<CONV_BLOCKS / 2, 256>>>(X, CONV_BLOCKS / 2 * 256);
    enorm_kernel      <<<128, 256>>>(E);
    vq_mma_kernel     <<<N_TOK / 64, 256, GSMEM>>>(X);   // launch #4 -> profiled
    recheck_kernel    <<<4096, 256>>>(X, E);
    vq_epilogue_kernel<<<N_TOK / 4, 256>>>(X, E, out_q, out_idx, out_enc);
    vq_finalize_kernel<<<1, 256>>>(out_loss, out_perp);
}